// round 14
// baseline (speedup 1.0000x reference)
#include <cuda_runtime.h>
#include <cuda_fp16.h>
#include <math.h>

// ---------------- problem constants ----------------
static constexpr int kBS = 2;
static constexpr int kC  = 128;
static constexpr int kH  = 80;
static constexpr int kW  = 160;
static constexpr int kHW = kH * kW;          // 12800
static constexpr int kN  = kBS * kHW;        // 25600 pixels
static constexpr int kP  = 9;
static constexpr int kOUT_ELEMS = kBS * kC * kHW;      // 3,276,800
static constexpr int kKP_ELEMS  = kN * kP * 2;         // 460,800 per branch

struct __align__(8)  H4 { __half2 a, b; };
struct __align__(16) H8 { __half2 a, b, c, d; };

// ---------------- scratch (device globals; no allocation) ----------------
__device__ __align__(16) __half g_vals_ctx[kN * kC];   // pixel-major ctx value features (fp16)
__device__ __align__(16) __half g_vals_geo[kN * kC];
__device__ float g_w_ctx[kN * 72];           // raw (pre-softmax) attention logits
__device__ float g_w_geo[kN * 72];
__device__ __align__(16) float g_kp[2 * kN * kP * 2];  // keypoints per branch
__device__ __align__(16) __half g_W16[400 * 128];      // fp16 fused (gamma-scaled) weights, [o][k]
__device__ __align__(16) float  g_Wkp[18 * 128];       // fp32 keypoint weights, [o][k]
__device__ float g_Rs[448];                  // rowsum of (quantized) gamma-scaled weights
__device__ float g_Bt[448];                  // W@beta + bias
__device__ __align__(16) __half g_OW16[128 * 256];     // fp16 out_w, [o][k] (native layout)
__device__ __align__(16) __half g_feat[kN * 256];      // aggregated features, px-major (13.1 MB)

// ---------------- mma / async helpers ----------------
__device__ __forceinline__ unsigned smem_u32(const void* p) {
    return (unsigned)__cvta_generic_to_shared(p);
}
__device__ __forceinline__ void ldsm_x4(unsigned& r0, unsigned& r1, unsigned& r2, unsigned& r3,
                                        unsigned addr) {
    asm volatile("ldmatrix.sync.aligned.m8n8.x4.shared.b16 {%0,%1,%2,%3}, [%4];"
                 : "=r"(r0), "=r"(r1), "=r"(r2), "=r"(r3) : "r"(addr));
}
__device__ __forceinline__ void mma16816(float& d0, float& d1, float& d2, float& d3,
                                         unsigned a0, unsigned a1, unsigned a2, unsigned a3,
                                         unsigned b0, unsigned b1) {
    asm volatile("mma.sync.aligned.m16n8k16.row.col.f32.f16.f16.f32 "
                 "{%0,%1,%2,%3}, {%4,%5,%6,%7}, {%8,%9}, {%0,%1,%2,%3};"
                 : "+f"(d0), "+f"(d1), "+f"(d2), "+f"(d3)
                 : "r"(a0), "r"(a1), "r"(a2), "r"(a3), "r"(b0), "r"(b1));
}
__device__ __forceinline__ void cp_async16(unsigned dst, const void* src) {
    asm volatile("cp.async.cg.shared.global [%0], [%1], 16;" :: "r"(dst), "l"(src));
}

// ---------------- merged prep kernel ----------------
__global__ void prep_all(
    const float* __restrict__ vc_w, const float* __restrict__ vc_b,
    const float* __restrict__ vg_w, const float* __restrict__ vg_b,
    const float* __restrict__ wc_w, const float* __restrict__ wc_b,
    const float* __restrict__ wg_w, const float* __restrict__ wg_b,
    const float* __restrict__ kpc_w, const float* __restrict__ kpc_b,
    const float* __restrict__ kpg_w, const float* __restrict__ kpg_b,
    const float* __restrict__ ln_g, const float* __restrict__ ln_b,
    const float* __restrict__ lnc_g, const float* __restrict__ lnc_b,
    const float* __restrict__ lng_g, const float* __restrict__ lng_b,
    const float* __restrict__ out_w)
{
    const int k = threadIdx.x;   // 128 threads
    if (blockIdx.x >= 418) {
        const int o2 = blockIdx.x - 418;   // 0..127
        g_OW16[o2 * 256 + k]       = __float2half(out_w[o2 * 256 + k]);
        g_OW16[o2 * 256 + k + 128] = __float2half(out_w[o2 * 256 + k + 128]);
        return;
    }
    __shared__ float r1[4], r2[4];
    const int o = blockIdx.x;        // 0..417
    const float* Wrow; float bias; const float* ga; const float* be;
    if (o < 128)      { Wrow = vc_w  + o * 128;         bias = vc_b[o];        ga = lnc_g; be = lnc_b; }
    else if (o < 256) { Wrow = vg_w  + (o - 128) * 128; bias = vg_b[o - 128];  ga = lng_g; be = lng_b; }
    else if (o < 328) { Wrow = wc_w  + (o - 256) * 128; bias = wc_b[o - 256];  ga = ln_g;  be = ln_b;  }
    else if (o < 400) { Wrow = wg_w  + (o - 328) * 128; bias = wg_b[o - 328];  ga = ln_g;  be = ln_b;  }
    else if (o < 409) { Wrow = kpc_w + (o - 400) * 128; bias = kpc_b[o - 400]; ga = ln_g;  be = ln_b;  }
    else              { Wrow = kpg_w + (o - 409) * 128; bias = kpg_b[o - 409]; ga = ln_g;  be = ln_b;  }
    const float w  = Wrow[k];
    const float wg = w * ga[k];
    float s1;
    if (o < 400) {
        const __half h = __float2half(wg);
        g_W16[o * 128 + k] = h;
        s1 = __half2float(h);            // rowsum must match QUANTIZED weights
    } else {
        g_Wkp[(o - 400) * 128 + k] = wg;
        s1 = wg;
    }
    float s2 = w * be[k];
    #pragma unroll
    for (int off = 16; off; off >>= 1) {
        s1 += __shfl_down_sync(0xffffffffu, s1, off);
        s2 += __shfl_down_sync(0xffffffffu, s2, off);
    }
    if ((k & 31) == 0) { r1[k >> 5] = s1; r2[k >> 5] = s2; }
    __syncthreads();
    if (k == 0) {
        g_Rs[o] = r1[0] + r1[1] + r1[2] + r1[3];
        g_Bt[o] = r2[0] + r2[1] + r2[2] + r2[3] + bias;
    }
}

// ---------------- kernel 1: per-source passes, smem-resident weights, 3 CTAs ----------------
// (round-13 version, unchanged)
static constexpr int kS16 = 136;        // halfs per row; 272 B (16B multiple -> ldmatrix legal)
static constexpr int kK1Smem = 57088;   // x3 CTAs = 171,264 B -> ~62KB L1D for g_Wkp/g_Rs/g_Bt

struct K1Shared {
    __half* xs16; __half* wbuf; float* mean_sm; float* istd_sm;
};

template <int MODE>   // 0: vc->g_vals_ctx, 1: vg->g_vals_geo, 2: wc/wg logits + keypoints
__device__ __forceinline__ void k1_pass(
    const K1Shared& S, const float* __restrict__ srcp, int wrow0, int ntile,
    int nb, int b, int hwb,
    const float* __restrict__ anc_c, const float* __restrict__ anc_g,
    float* __restrict__ d_out, int out_size)
{
    const int t    = threadIdx.x;
    const int lane = t & 31;
    const int wrp  = t >> 5;
    const int px   = t >> 2;        // 0..63
    const int c0   = t & 3;         // channel quarter

    // ---- 1. async-copy pass weights to smem ----
    {
        const unsigned wb0 = smem_u32(S.wbuf);
        for (int i = t; i < ntile * 128; i += 256) {
            const int r  = i >> 4;          // row (256 data bytes per row)
            const int kq = i & 15;          // 16B chunk within row
            cp_async16(wb0 + (unsigned)(r * kS16 * 2 + kq * 16),
                       g_W16 + (wrow0 + r) * 128 + kq * 8);
        }
        asm volatile("cp.async.commit_group;" ::: "memory");
    }

    // ---- 2. stage x (fp32 gmem -> fp16 smem), LN stats via quad shuffle, kp dots ----
    float pd[18];
    if (MODE == 2) {
        #pragma unroll
        for (int o = 0; o < 18; o++) pd[o] = 0.f;
    }
    float su = 0.f, sq = 0.f;
    {
        const float* gp = srcp + b * kC * kHW + hwb + px;
        __half* hrow = S.xs16 + px * kS16 + c0 * 32;
        #pragma unroll
        for (int jc = 0; jc < 8; jc++) {
            const int c = c0 * 32 + jc * 4;
            const float v0 = gp[(c + 0) * kHW];
            const float v1 = gp[(c + 1) * kHW];
            const float v2 = gp[(c + 2) * kHW];
            const float v3 = gp[(c + 3) * kHW];
            su += (v0 + v1) + (v2 + v3);
            sq += (v0 * v0 + v1 * v1) + (v2 * v2 + v3 * v3);
            H4 h;
            h.a = __floats2half2_rn(v0, v1);
            h.b = __floats2half2_rn(v2, v3);
            *reinterpret_cast<H4*>(hrow + jc * 4) = h;
            if (MODE == 2) {
                #pragma unroll
                for (int o = 0; o < 18; o++) {
                    const float4 w4 = *reinterpret_cast<const float4*>(g_Wkp + o * 128 + c);
                    pd[o] += w4.x * v0 + w4.y * v1 + w4.z * v2 + w4.w * v3;
                }
            }
        }
    }
    // quad reduce (4 lanes of one pixel are adjacent)
    su += __shfl_xor_sync(0xffffffffu, su, 1);
    sq += __shfl_xor_sync(0xffffffffu, sq, 1);
    su += __shfl_xor_sync(0xffffffffu, su, 2);
    sq += __shfl_xor_sync(0xffffffffu, sq, 2);
    const float m_px  = su * (1.f / 128.f);
    const float var_px = sq * (1.f / 128.f) - m_px * m_px;
    const float is_px = rsqrtf(var_px + 1e-5f);
    if (c0 == 0) { S.mean_sm[px] = m_px; S.istd_sm[px] = is_px; }

    if (MODE == 2) {
        #pragma unroll
        for (int o = 0; o < 18; o++) {
            pd[o] += __shfl_xor_sync(0xffffffffu, pd[o], 1);
            pd[o] += __shfl_xor_sync(0xffffffffu, pd[o], 2);
        }
        // keypoint epilogue: all operands in-register (quad leaders write)
        if (c0 == 0) {
            const int n = nb + px;
            #pragma unroll
            for (int o = 0; o < 18; o++) {
                const float off = (pd[o] - m_px * g_Rs[400 + o]) * is_px + g_Bt[400 + o];
                const int br = (o < 9) ? 0 : 1;
                const int p  = o - (br ? 9 : 0);
                const int ai = (n * kP + p) * 2;
                const float* anc = br ? anc_g : anc_c;
                const float kx = anc[ai] + off;
                const float ky = anc[ai + 1];
                *reinterpret_cast<float2*>(&g_kp[br * (kN * kP * 2) + ai]) = make_float2(kx, ky);
                if (out_size >= kOUT_ELEMS + 2 * kKP_ELEMS) {
                    *reinterpret_cast<float2*>(d_out + kOUT_ELEMS + br * kKP_ELEMS + ai) =
                        make_float2(kx, ky);
                }
            }
        }
    }

    asm volatile("cp.async.wait_group 0;" ::: "memory");
    __syncthreads();   // xs16 + stats + wbuf all visible

    // ---- 3. MMA: warp owns m-tile (16 px); B-frags from smem ----
    {
        const int mt  = wrp >> 1;        // 0..3
        const int par = wrp & 1;
        const int pxl = mt * 16 + (lane >> 2), pxh = pxl + 8;
        unsigned A[8][4];
        const unsigned abase = smem_u32(S.xs16) +
            (unsigned)(((mt * 16 + (lane & 15)) * kS16 + ((lane >> 4) * 8)) * 2);
        #pragma unroll
        for (int kk = 0; kk < 8; kk++)
            ldsm_x4(A[kk][0], A[kk][1], A[kk][2], A[kk][3], abase + kk * 32);

        const float ml = S.mean_sm[pxl], il = S.istd_sm[pxl];
        const float mh = S.mean_sm[pxh], ih = S.istd_sm[pxh];
        const int nl = nb + pxl, nh = nb + pxh;

        for (int T = par; T < ntile; T += 2) {
            const __half* wb = S.wbuf + (T * 8 + (lane >> 2)) * kS16 + (lane & 3) * 2;
            float d0 = 0.f, d1 = 0.f, d2 = 0.f, d3 = 0.f;
            #pragma unroll
            for (int kk = 0; kk < 8; kk++) {
                const unsigned b0 = *reinterpret_cast<const unsigned*>(wb + kk * 16);
                const unsigned b1 = *reinterpret_cast<const unsigned*>(wb + kk * 16 + 8);
                mma16816(d0, d1, d2, d3, A[kk][0], A[kk][1], A[kk][2], A[kk][3], b0, b1);
            }
            const int opl = T * 8 + 2 * (lane & 3);
            const int og  = wrow0 + opl;
            const float rs0 = g_Rs[og], rs1 = g_Rs[og + 1];
            const float bt0 = g_Bt[og], bt1 = g_Bt[og + 1];
            const float v00 = (d0 - ml * rs0) * il + bt0;
            const float v01 = (d1 - ml * rs1) * il + bt1;
            const float v10 = (d2 - mh * rs0) * ih + bt0;
            const float v11 = (d3 - mh * rs1) * ih + bt1;
            if (MODE == 0) {
                *reinterpret_cast<__half2*>(&g_vals_ctx[nl * kC + opl]) = __floats2half2_rn(v00, v01);
                *reinterpret_cast<__half2*>(&g_vals_ctx[nh * kC + opl]) = __floats2half2_rn(v10, v11);
            } else if (MODE == 1) {
                *reinterpret_cast<__half2*>(&g_vals_geo[nl * kC + opl]) = __floats2half2_rn(v00, v01);
                *reinterpret_cast<__half2*>(&g_vals_geo[nh * kC + opl]) = __floats2half2_rn(v10, v11);
            } else {
                float* dst; int col;
                if (opl < 72) { dst = g_w_ctx; col = opl; }
                else          { dst = g_w_geo; col = opl - 72; }
                *reinterpret_cast<float2*>(&dst[nl * 72 + col]) = make_float2(v00, v01);
                *reinterpret_cast<float2*>(&dst[nh * 72 + col]) = make_float2(v10, v11);
            }
        }
    }
}

__global__ __launch_bounds__(256, 3) void k1_ln_gemm(
    const float* __restrict__ match, const float* __restrict__ context,
    const float* __restrict__ geometric,
    const float* __restrict__ anc_c, const float* __restrict__ anc_g,
    float* __restrict__ d_out, int out_size)
{
    extern __shared__ unsigned char smraw[];
    K1Shared S;
    S.xs16    = reinterpret_cast<__half*>(smraw);
    S.wbuf    = reinterpret_cast<__half*>(smraw + 17408);
    S.mean_sm = reinterpret_cast<float*>(smraw + 56576);
    S.istd_sm = reinterpret_cast<float*>(smraw + 56832);

    const int nb  = blockIdx.x * 64;
    const int b   = nb / kHW;
    const int hwb = nb - b * kHW;

    k1_pass<0>(S, context,   0,   16, nb, b, hwb, anc_c, anc_g, d_out, out_size);
    __syncthreads();
    k1_pass<1>(S, geometric, 128, 16, nb, b, hwb, anc_c, anc_g, d_out, out_size);
    __syncthreads();
    k1_pass<2>(S, match,     256, 18, nb, b, hwb, anc_c, anc_g, d_out, out_size);
}

// ---------------- kernel 2a: softmax + corners + deformable gather -> g_feat ----------------
// smem: cwh 9216 | cidx 4608 | wts 9216 | msm 128 = 23,168 B; 6 CTAs/SM target
static constexpr int kK2aSmem = 23168;

__global__ __launch_bounds__(256, 6) void k2a_gather(
    const float* __restrict__ mask)
{
    extern __shared__ unsigned char smraw[];
    __half2* cwh  = reinterpret_cast<__half2*>(smraw);
    short*  cidx  = reinterpret_cast<short*>(smraw + 9216);
    __half* wts   = reinterpret_cast<__half*>(smraw + 13824);
    float*  msm   = reinterpret_cast<float*>(smraw + 23040);

    const int t   = threadIdx.x;
    const int nb  = blockIdx.x * 32;
    const int b   = nb / kHW;
    const int hwb = nb - b * kHW;

    if (t < 32) msm[t] = mask[b * kHW + hwb + t];

    for (int task = t; task < 512; task += 256) {
        const int px = task >> 4, bg = task & 15;
        const int br = bg >> 3, g = bg & 7;
        const float* base = (br ? g_w_geo : g_w_ctx) + (nb + px) * 72 + g;
        float e[kP];
        float mx = __ldg(base);
        #pragma unroll
        for (int p = 1; p < kP; p++) { e[p] = __ldg(base + p * 8); mx = fmaxf(mx, e[p]); }
        e[0] = __ldg(base);
        float s = 0.f;
        #pragma unroll
        for (int p = 0; p < kP; p++) { e[p] = __expf(e[p] - mx); s += e[p]; }
        const float inv = 1.f / s;
        __half* dst = wts + px * 144 + br * 72 + g;
        #pragma unroll
        for (int p = 0; p < kP; p++) dst[p * 8] = __float2half(e[p] * inv);
    }

    for (int task = t; task < 576; task += 256) {
        const int px = task / 18, j = task - px * 18;
        const int br = j / 9, p = j - br * 9;
        const int n = nb + px;
        const float* kp = g_kp + br * (kN * kP * 2) + (n * kP + p) * 2;
        const float x = kp[0] * (float)kW - 0.5f;
        const float y = kp[1] * (float)kH - 0.5f;
        const float xf = floorf(x), yf = floorf(y);
        const float dx = x - xf, dy = y - yf;
        const int x0 = (int)xf, y0 = (int)yf;
        const int o = (px * 18 + j) * 4;
        #pragma unroll
        for (int c = 0; c < 4; c++) {
            const int xi = x0 + (c & 1), yi = y0 + (c >> 1);
            const bool valid = (xi >= 0) && (xi < kW) && (yi >= 0) && (yi < kH);
            const int xc = min(max(xi, 0), kW - 1), yc = min(max(yi, 0), kH - 1);
            const float wt = ((c & 1) ? dx : 1.f - dx) * ((c >> 1) ? dy : 1.f - dy);
            cwh[o + c]  = __half2half2(__float2half(valid ? wt : 0.f));
            cidx[o + c] = (short)(yc * kW + xc);
        }
    }
    __syncthreads();

    // gather: 8 channels/thread via LDG.128, fp16 corners + fp32 softmax accumulation.
    {
        const int lane = t & 31;
        const int pq   = t >> 5;        // 0..7
        const int c8   = lane & 15;
        const int br   = lane >> 4;
        const __half* vals = (br ? g_vals_geo : g_vals_ctx) + b * kHW * kC + c8 * 8;
        const int gidx = c8 >> 1;       // group = (c8*8)/16
        #pragma unroll
        for (int chunk = 0; chunk < 4; chunk++) {
            const int px = chunk * 8 + pq;
            float a0 = 0.f, a1 = 0.f, a2 = 0.f, a3 = 0.f;
            float a4 = 0.f, a5 = 0.f, a6 = 0.f, a7 = 0.f;
            const __half* wtp = wts + px * 144 + br * 72 + gidx;
            const uint4*  cwp4 = reinterpret_cast<const uint4*>(cwh + (px * 18 + br * 9) * 4);
            const short4* idp4 = reinterpret_cast<const short4*>(cidx + (px * 18 + br * 9) * 4);
            #pragma unroll
            for (int p = 0; p < kP; p++) {
                const float wp = __half2float(wtp[p * 8]);
                const uint4  cu = cwp4[p];
                const short4 iv = idp4[p];
                const __half2 zero = __float2half2_rn(0.f);
                __half2 s01 = zero, s23 = zero, s45 = zero, s67 = zero;
                #pragma unroll
                for (int c = 0; c < 4; c++) {
                    const unsigned cb = (c == 0) ? cu.x : (c == 1) ? cu.y : (c == 2) ? cu.z : cu.w;
                    const int     idx = (c == 0) ? iv.x : (c == 1) ? iv.y : (c == 2) ? iv.z : iv.w;
                    const __half2 ch = *reinterpret_cast<const __half2*>(&cb);
                    const H8 r = *reinterpret_cast<const H8*>(vals + (int)idx * kC);
                    s01 = __hfma2(ch, r.a, s01);
                    s23 = __hfma2(ch, r.b, s23);
                    s45 = __hfma2(ch, r.c, s45);
                    s67 = __hfma2(ch, r.d, s67);
                }
                const float2 f0 = __half22float2(s01), f1 = __half22float2(s23);
                const float2 f2 = __half22float2(s45), f3 = __half22float2(s67);
                a0 = fmaf(wp, f0.x, a0); a1 = fmaf(wp, f0.y, a1);
                a2 = fmaf(wp, f1.x, a2); a3 = fmaf(wp, f1.y, a3);
                a4 = fmaf(wp, f2.x, a4); a5 = fmaf(wp, f2.y, a5);
                a6 = fmaf(wp, f3.x, a6); a7 = fmaf(wp, f3.y, a7);
            }
            const float sc = br ? 1.f : msm[px];
            H8 h;
            h.a = __floats2half2_rn(a0 * sc, a1 * sc);
            h.b = __floats2half2_rn(a2 * sc, a3 * sc);
            h.c = __floats2half2_rn(a4 * sc, a5 * sc);
            h.d = __floats2half2_rn(a6 * sc, a7 * sc);
            // coalesced: whole warp writes one px row (512 B) per chunk
            *reinterpret_cast<H8*>(g_feat + (nb + px) * 256 + (br * 128 + c8 * 8)) = h;
        }
    }
}

// ---------------- kernel 2b: 256 -> 128 output conv (pure MMA, no smem) ----------------
__global__ __launch_bounds__(256) void k2b_outconv(
    const float* __restrict__ out_b, float* __restrict__ d_out)
{
    const int t    = threadIdx.x;
    const int wrp  = t >> 5, lane = t & 31;
    const int nb   = blockIdx.x * 64;
    const int b    = nb / kHW;
    const int hwb  = nb - b * kHW;
    const int o0   = wrp * 16;
    const int r    = lane >> 2;
    const int c2   = (lane & 3) * 2;

    const __half* Arow0 = g_OW16 + (o0 + r) * 256 + c2;
    const __half* Arow1 = Arow0 + 8 * 256;
    const __half* fbase = g_feat + (long long)nb * 256 + c2;

    float d[8][4];
    #pragma unroll
    for (int nt = 0; nt < 8; nt++)
        #pragma unroll
        for (int q = 0; q < 4; q++) d[nt][q] = 0.f;

    #pragma unroll
    for (int kk = 0; kk < 16; kk++) {
        const unsigned a0 = *reinterpret_cast<const unsigned*>(Arow0 + kk * 16);
        const unsigned a2 = *reinterpret_cast<const unsigned*>(Arow0 + kk * 16 + 8);
        const unsigned a1 = *reinterpret_cast<const unsigned*>(Arow1 + kk * 16);
        const unsigned a3 = *reinterpret_cast<const unsigned*>(Arow1 + kk * 16 + 8);
        #pragma unroll
        for (int nt = 0; nt < 8; nt++) {
            const __half* bp = fbase + (nt * 8 + r) * 256 + kk * 16;
            const unsigned b0 = *reinterpret_cast<const unsigned*>(bp);
            const unsigned b1 = *reinterpret_cast<const unsigned*>(bp + 8);
            mma16816(d[nt][0], d[nt][1], d[nt][2], d[nt][3], a0, a1, a2, a3, b0, b1);
        }
    }
    const float bb0 = out_b[o0 + r];
    const float bb1 = out_b[o0 + r + 8];
    float* obase = d_out + b * kC * kHW + hwb;
    #pragma unroll
    for (int nt = 0; nt < 8; nt++) {
        const int px = nt * 8 + c2;
        *reinterpret_cast<float2*>(obase + (o0 + r) * kHW + px) =
            make_float2(d[nt][0] + bb0, d[nt][1] + bb0);
        *reinterpret_cast<float2*>(obase + (o0 + r + 8) * kHW + px) =
            make_float2(d[nt][2] + bb1, d[nt][3] + bb1);
    }
}

// ---------------- launch ----------------
extern "C" void kernel_launch(void* const* d_in, const int* in_sizes, int n_in,
                              void* d_out, int out_size)
{
    const float* mask      = (const float*)d_in[0];
    const float* match     = (const float*)d_in[1];
    const float* context   = (const float*)d_in[2];
    const float* geometric = (const float*)d_in[3];
    const float* anc_c     = (const float*)d_in[4];
    const float* anc_g     = (const float*)d_in[5];
    const float* ln_g  = (const float*)d_in[6];
    const float* ln_b  = (const float*)d_in[7];
    const float* lnc_g = (const float*)d_in[8];
    const float* lnc_b = (const float*)d_in[9];
    const float* lng_g = (const float*)d_in[10];
    const float* lng_b = (const float*)d_in[11];
    const float* wc_w  = (const float*)d_in[12];
    const float* wc_b  = (const float*)d_in[13];
    const float* wg_w  = (const float*)d_in[14];
    const float* wg_b  = (const float*)d_in[15];
    const float* vc_w  = (const float*)d_in[16];
    const float* vc_b  = (const float*)d_in[17];
    const float* vg_w  = (const float*)d_in[18];
    const float* vg_b  = (const float*)d_in[19];
    const float* out_w = (const float*)d_in[20];
    const float* out_b = (const float*)d_in[21];
    const float* kpc_w = (const float*)d_in[22];
    const float* kpc_b = (const float*)d_in[23];
    const float* kpg_w = (const float*)d_in[24];
    const float* kpg_b = (const float*)d_in[25];
    float* out = (float*)d_out;

    cudaFuncSetAttribute(k1_ln_gemm, cudaFuncAttributeMaxDynamicSharedMemorySize, kK1Smem);
    cudaFuncSetAttribute(k2a_gather, cudaFuncAttributeMaxDynamicSharedMemorySize, kK2aSmem);

    prep_all<<<546, 128>>>(vc_w, vc_b, vg_w, vg_b, wc_w, wc_b, wg_w, wg_b,
                           kpc_w, kpc_b, kpg_w, kpg_b,
                           ln_g, ln_b, lnc_g, lnc_b, lng_g, lng_b, out_w);
    k1_ln_gemm<<<kN / 64, 256, kK1Smem>>>(match, context, geometric, anc_c, anc_g, out, out_size);
    k2a_gather<<<kN / 32, 256, kK2aSmem>>>(mask);
    k2b_outconv<<<kN / 64, 256>>>(out_b, out);
}

// round 15
// speedup vs baseline: 1.1927x; 1.1927x over previous
#include <cuda_runtime.h>
#include <cuda_fp16.h>
#include <math.h>

// ---------------- problem constants ----------------
static constexpr int kBS = 2;
static constexpr int kC  = 128;
static constexpr int kH  = 80;
static constexpr int kW  = 160;
static constexpr int kHW = kH * kW;          // 12800
static constexpr int kN  = kBS * kHW;        // 25600 pixels
static constexpr int kP  = 9;
static constexpr int kOUT_ELEMS = kBS * kC * kHW;      // 3,276,800
static constexpr int kKP_ELEMS  = kN * kP * 2;         // 460,800 per branch

struct __align__(8)  H4 { __half2 a, b; };
struct __align__(16) H8 { __half2 a, b, c, d; };

// ---------------- scratch (device globals; no allocation) ----------------
__device__ __align__(16) __half g_vals_ctx[kN * kC];   // pixel-major ctx value features (fp16)
__device__ __align__(16) __half g_vals_geo[kN * kC];
__device__ float g_w_ctx[kN * 72];           // raw (pre-softmax) attention logits
__device__ float g_w_geo[kN * 72];
__device__ __align__(16) float g_kp[2 * kN * kP * 2];  // keypoints per branch
__device__ __align__(16) __half g_W16[400 * 128];      // fp16 fused (gamma-scaled) weights, [o][k]
__device__ __align__(16) float  g_Wkp[18 * 128];       // fp32 keypoint weights, [o][k]
__device__ float g_Rs[448];                  // rowsum of (quantized) gamma-scaled weights
__device__ float g_Bt[448];                  // W@beta + bias
__device__ __align__(16) __half g_OW16[128 * 256];     // fp16 out_w, [o][k] (native layout)
__device__ __align__(16) __half g_feat[kN * 256];      // aggregated features, px-major (13.1 MB)

// ---------------- mma / async helpers ----------------
__device__ __forceinline__ unsigned smem_u32(const void* p) {
    return (unsigned)__cvta_generic_to_shared(p);
}
__device__ __forceinline__ void ldsm_x4(unsigned& r0, unsigned& r1, unsigned& r2, unsigned& r3,
                                        unsigned addr) {
    asm volatile("ldmatrix.sync.aligned.m8n8.x4.shared.b16 {%0,%1,%2,%3}, [%4];"
                 : "=r"(r0), "=r"(r1), "=r"(r2), "=r"(r3) : "r"(addr));
}
__device__ __forceinline__ void mma16816(float& d0, float& d1, float& d2, float& d3,
                                         unsigned a0, unsigned a1, unsigned a2, unsigned a3,
                                         unsigned b0, unsigned b1) {
    asm volatile("mma.sync.aligned.m16n8k16.row.col.f32.f16.f16.f32 "
                 "{%0,%1,%2,%3}, {%4,%5,%6,%7}, {%8,%9}, {%0,%1,%2,%3};"
                 : "+f"(d0), "+f"(d1), "+f"(d2), "+f"(d3)
                 : "r"(a0), "r"(a1), "r"(a2), "r"(a3), "r"(b0), "r"(b1));
}
__device__ __forceinline__ void cp_async16(unsigned dst, const void* src) {
    asm volatile("cp.async.cg.shared.global [%0], [%1], 16;" :: "r"(dst), "l"(src));
}

// ---------------- merged prep kernel ----------------
__global__ void prep_all(
    const float* __restrict__ vc_w, const float* __restrict__ vc_b,
    const float* __restrict__ vg_w, const float* __restrict__ vg_b,
    const float* __restrict__ wc_w, const float* __restrict__ wc_b,
    const float* __restrict__ wg_w, const float* __restrict__ wg_b,
    const float* __restrict__ kpc_w, const float* __restrict__ kpc_b,
    const float* __restrict__ kpg_w, const float* __restrict__ kpg_b,
    const float* __restrict__ ln_g, const float* __restrict__ ln_b,
    const float* __restrict__ lnc_g, const float* __restrict__ lnc_b,
    const float* __restrict__ lng_g, const float* __restrict__ lng_b,
    const float* __restrict__ out_w)
{
    const int k = threadIdx.x;   // 128 threads
    if (blockIdx.x >= 418) {
        const int o2 = blockIdx.x - 418;   // 0..127
        g_OW16[o2 * 256 + k]       = __float2half(out_w[o2 * 256 + k]);
        g_OW16[o2 * 256 + k + 128] = __float2half(out_w[o2 * 256 + k + 128]);
        return;
    }
    __shared__ float r1[4], r2[4];
    const int o = blockIdx.x;        // 0..417
    const float* Wrow; float bias; const float* ga; const float* be;
    if (o < 128)      { Wrow = vc_w  + o * 128;         bias = vc_b[o];        ga = lnc_g; be = lnc_b; }
    else if (o < 256) { Wrow = vg_w  + (o - 128) * 128; bias = vg_b[o - 128];  ga = lng_g; be = lng_b; }
    else if (o < 328) { Wrow = wc_w  + (o - 256) * 128; bias = wc_b[o - 256];  ga = ln_g;  be = ln_b;  }
    else if (o < 400) { Wrow = wg_w  + (o - 328) * 128; bias = wg_b[o - 328];  ga = ln_g;  be = ln_b;  }
    else if (o < 409) { Wrow = kpc_w + (o - 400) * 128; bias = kpc_b[o - 400]; ga = ln_g;  be = ln_b;  }
    else              { Wrow = kpg_w + (o - 409) * 128; bias = kpg_b[o - 409]; ga = ln_g;  be = ln_b;  }
    const float w  = Wrow[k];
    const float wg = w * ga[k];
    float s1;
    if (o < 400) {
        const __half h = __float2half(wg);
        g_W16[o * 128 + k] = h;
        s1 = __half2float(h);            // rowsum must match QUANTIZED weights
    } else {
        g_Wkp[(o - 400) * 128 + k] = wg;
        s1 = wg;
    }
    float s2 = w * be[k];
    #pragma unroll
    for (int off = 16; off; off >>= 1) {
        s1 += __shfl_down_sync(0xffffffffu, s1, off);
        s2 += __shfl_down_sync(0xffffffffu, s2, off);
    }
    if ((k & 31) == 0) { r1[k >> 5] = s1; r2[k >> 5] = s2; }
    __syncthreads();
    if (k == 0) {
        g_Rs[o] = r1[0] + r1[1] + r1[2] + r1[3];
        g_Bt[o] = r2[0] + r2[1] + r2[2] + r2[3] + bias;
    }
}

// ---------------- kernel 1: per-source passes, smem-resident weights, 3 CTAs ----------------
static constexpr int kS16 = 136;        // halfs per row; 272 B (16B multiple -> ldmatrix legal)
static constexpr int kK1Smem = 57088;   // x3 CTAs = 171,264 B -> ~62KB L1D for g_Wkp/g_Rs/g_Bt

struct K1Shared {
    __half* xs16; __half* wbuf; float* mean_sm; float* istd_sm;
};

template <int MODE>   // 0: vc->g_vals_ctx, 1: vg->g_vals_geo, 2: wc/wg logits + keypoints
__device__ __forceinline__ void k1_pass(
    const K1Shared& S, const float* __restrict__ srcp, int wrow0, int ntile,
    int nb, int b, int hwb,
    const float* __restrict__ anc_c, const float* __restrict__ anc_g,
    float* __restrict__ d_out, int out_size)
{
    const int t    = threadIdx.x;
    const int lane = t & 31;
    const int wrp  = t >> 5;
    const int px   = t >> 2;        // 0..63
    const int c0   = t & 3;         // channel quarter

    // ---- 1. async-copy pass weights to smem ----
    {
        const unsigned wb0 = smem_u32(S.wbuf);
        for (int i = t; i < ntile * 128; i += 256) {
            const int r  = i >> 4;          // row (256 data bytes per row)
            const int kq = i & 15;          // 16B chunk within row
            cp_async16(wb0 + (unsigned)(r * kS16 * 2 + kq * 16),
                       g_W16 + (wrow0 + r) * 128 + kq * 8);
        }
        asm volatile("cp.async.commit_group;" ::: "memory");
    }

    // ---- 2. stage x (fp32 gmem -> fp16 smem), LN stats via quad shuffle, kp dots ----
    float pd[18];
    if (MODE == 2) {
        #pragma unroll
        for (int o = 0; o < 18; o++) pd[o] = 0.f;
    }
    float su = 0.f, sq = 0.f;
    {
        const float* gp = srcp + b * kC * kHW + hwb + px;
        __half* hrow = S.xs16 + px * kS16 + c0 * 32;
        #pragma unroll
        for (int jc = 0; jc < 8; jc++) {
            const int c = c0 * 32 + jc * 4;
            const float v0 = gp[(c + 0) * kHW];
            const float v1 = gp[(c + 1) * kHW];
            const float v2 = gp[(c + 2) * kHW];
            const float v3 = gp[(c + 3) * kHW];
            su += (v0 + v1) + (v2 + v3);
            sq += (v0 * v0 + v1 * v1) + (v2 * v2 + v3 * v3);
            H4 h;
            h.a = __floats2half2_rn(v0, v1);
            h.b = __floats2half2_rn(v2, v3);
            *reinterpret_cast<H4*>(hrow + jc * 4) = h;
            if (MODE == 2) {
                #pragma unroll
                for (int o = 0; o < 18; o++) {
                    const float4 w4 = *reinterpret_cast<const float4*>(g_Wkp + o * 128 + c);
                    pd[o] += w4.x * v0 + w4.y * v1 + w4.z * v2 + w4.w * v3;
                }
            }
        }
    }
    // quad reduce (4 lanes of one pixel are adjacent)
    su += __shfl_xor_sync(0xffffffffu, su, 1);
    sq += __shfl_xor_sync(0xffffffffu, sq, 1);
    su += __shfl_xor_sync(0xffffffffu, su, 2);
    sq += __shfl_xor_sync(0xffffffffu, sq, 2);
    const float m_px  = su * (1.f / 128.f);
    const float var_px = sq * (1.f / 128.f) - m_px * m_px;
    const float is_px = rsqrtf(var_px + 1e-5f);
    if (c0 == 0) { S.mean_sm[px] = m_px; S.istd_sm[px] = is_px; }

    if (MODE == 2) {
        #pragma unroll
        for (int o = 0; o < 18; o++) {
            pd[o] += __shfl_xor_sync(0xffffffffu, pd[o], 1);
            pd[o] += __shfl_xor_sync(0xffffffffu, pd[o], 2);
        }
        // keypoint epilogue: all operands in-register (quad leaders write)
        if (c0 == 0) {
            const int n = nb + px;
            #pragma unroll
            for (int o = 0; o < 18; o++) {
                const float off = (pd[o] - m_px * g_Rs[400 + o]) * is_px + g_Bt[400 + o];
                const int br = (o < 9) ? 0 : 1;
                const int p  = o - (br ? 9 : 0);
                const int ai = (n * kP + p) * 2;
                const float* anc = br ? anc_g : anc_c;
                const float kx = anc[ai] + off;
                const float ky = anc[ai + 1];
                *reinterpret_cast<float2*>(&g_kp[br * (kN * kP * 2) + ai]) = make_float2(kx, ky);
                if (out_size >= kOUT_ELEMS + 2 * kKP_ELEMS) {
                    *reinterpret_cast<float2*>(d_out + kOUT_ELEMS + br * kKP_ELEMS + ai) =
                        make_float2(kx, ky);
                }
            }
        }
    }

    asm volatile("cp.async.wait_group 0;" ::: "memory");
    __syncthreads();   // xs16 + stats + wbuf all visible

    // ---- 3. MMA: warp owns m-tile (16 px); B-frags from smem ----
    {
        const int mt  = wrp >> 1;        // 0..3
        const int par = wrp & 1;
        const int pxl = mt * 16 + (lane >> 2), pxh = pxl + 8;
        unsigned A[8][4];
        const unsigned abase = smem_u32(S.xs16) +
            (unsigned)(((mt * 16 + (lane & 15)) * kS16 + ((lane >> 4) * 8)) * 2);
        #pragma unroll
        for (int kk = 0; kk < 8; kk++)
            ldsm_x4(A[kk][0], A[kk][1], A[kk][2], A[kk][3], abase + kk * 32);

        const float ml = S.mean_sm[pxl], il = S.istd_sm[pxl];
        const float mh = S.mean_sm[pxh], ih = S.istd_sm[pxh];
        const int nl = nb + pxl, nh = nb + pxh;

        for (int T = par; T < ntile; T += 2) {
            const __half* wb = S.wbuf + (T * 8 + (lane >> 2)) * kS16 + (lane & 3) * 2;
            float d0 = 0.f, d1 = 0.f, d2 = 0.f, d3 = 0.f;
            #pragma unroll
            for (int kk = 0; kk < 8; kk++) {
                const unsigned b0 = *reinterpret_cast<const unsigned*>(wb + kk * 16);
                const unsigned b1 = *reinterpret_cast<const unsigned*>(wb + kk * 16 + 8);
                mma16816(d0, d1, d2, d3, A[kk][0], A[kk][1], A[kk][2], A[kk][3], b0, b1);
            }
            const int opl = T * 8 + 2 * (lane & 3);
            const int og  = wrow0 + opl;
            const float rs0 = g_Rs[og], rs1 = g_Rs[og + 1];
            const float bt0 = g_Bt[og], bt1 = g_Bt[og + 1];
            const float v00 = (d0 - ml * rs0) * il + bt0;
            const float v01 = (d1 - ml * rs1) * il + bt1;
            const float v10 = (d2 - mh * rs0) * ih + bt0;
            const float v11 = (d3 - mh * rs1) * ih + bt1;
            if (MODE == 0) {
                *reinterpret_cast<__half2*>(&g_vals_ctx[nl * kC + opl]) = __floats2half2_rn(v00, v01);
                *reinterpret_cast<__half2*>(&g_vals_ctx[nh * kC + opl]) = __floats2half2_rn(v10, v11);
            } else if (MODE == 1) {
                *reinterpret_cast<__half2*>(&g_vals_geo[nl * kC + opl]) = __floats2half2_rn(v00, v01);
                *reinterpret_cast<__half2*>(&g_vals_geo[nh * kC + opl]) = __floats2half2_rn(v10, v11);
            } else {
                float* dst; int col;
                if (opl < 72) { dst = g_w_ctx; col = opl; }
                else          { dst = g_w_geo; col = opl - 72; }
                *reinterpret_cast<float2*>(&dst[nl * 72 + col]) = make_float2(v00, v01);
                *reinterpret_cast<float2*>(&dst[nh * 72 + col]) = make_float2(v10, v11);
            }
        }
    }
}

__global__ __launch_bounds__(256, 3) void k1_ln_gemm(
    const float* __restrict__ match, const float* __restrict__ context,
    const float* __restrict__ geometric,
    const float* __restrict__ anc_c, const float* __restrict__ anc_g,
    float* __restrict__ d_out, int out_size)
{
    extern __shared__ unsigned char smraw[];
    K1Shared S;
    S.xs16    = reinterpret_cast<__half*>(smraw);
    S.wbuf    = reinterpret_cast<__half*>(smraw + 17408);
    S.mean_sm = reinterpret_cast<float*>(smraw + 56576);
    S.istd_sm = reinterpret_cast<float*>(smraw + 56832);

    const int nb  = blockIdx.x * 64;
    const int b   = nb / kHW;
    const int hwb = nb - b * kHW;

    k1_pass<0>(S, context,   0,   16, nb, b, hwb, anc_c, anc_g, d_out, out_size);
    __syncthreads();
    k1_pass<1>(S, geometric, 128, 16, nb, b, hwb, anc_c, anc_g, d_out, out_size);
    __syncthreads();
    k1_pass<2>(S, match,     256, 18, nb, b, hwb, anc_c, anc_g, d_out, out_size);
}

// ---------------- kernel 2a: softmax + corners + deformable gather -> g_feat ----------------
// smem: cwh 9216 | cidx 4608 | wts 9216 | msm 128 = 23,168 B; 6 CTAs/SM
static constexpr int kK2aSmem = 23168;

__global__ __launch_bounds__(256, 6) void k2a_gather(
    const float* __restrict__ mask)
{
    extern __shared__ unsigned char smraw[];
    __half2* cwh  = reinterpret_cast<__half2*>(smraw);
    short*  cidx  = reinterpret_cast<short*>(smraw + 9216);
    __half* wts   = reinterpret_cast<__half*>(smraw + 13824);
    float*  msm   = reinterpret_cast<float*>(smraw + 23040);

    const int t   = threadIdx.x;
    const int nb  = blockIdx.x * 32;
    const int b   = nb / kHW;
    const int hwb = nb - b * kHW;

    if (t < 32) msm[t] = mask[b * kHW + hwb + t];

    for (int task = t; task < 512; task += 256) {
        const int px = task >> 4, bg = task & 15;
        const int br = bg >> 3, g = bg & 7;
        const float* base = (br ? g_w_geo : g_w_ctx) + (nb + px) * 72 + g;
        float e[kP];
        float mx = __ldg(base);
        #pragma unroll
        for (int p = 1; p < kP; p++) { e[p] = __ldg(base + p * 8); mx = fmaxf(mx, e[p]); }
        e[0] = __ldg(base);
        float s = 0.f;
        #pragma unroll
        for (int p = 0; p < kP; p++) { e[p] = __expf(e[p] - mx); s += e[p]; }
        const float inv = 1.f / s;
        __half* dst = wts + px * 144 + br * 72 + g;
        #pragma unroll
        for (int p = 0; p < kP; p++) dst[p * 8] = __float2half(e[p] * inv);
    }

    for (int task = t; task < 576; task += 256) {
        const int px = task / 18, j = task - px * 18;
        const int br = j / 9, p = j - br * 9;
        const int n = nb + px;
        const float* kp = g_kp + br * (kN * kP * 2) + (n * kP + p) * 2;
        const float x = kp[0] * (float)kW - 0.5f;
        const float y = kp[1] * (float)kH - 0.5f;
        const float xf = floorf(x), yf = floorf(y);
        const float dx = x - xf, dy = y - yf;
        const int x0 = (int)xf, y0 = (int)yf;
        const int o = (px * 18 + j) * 4;
        #pragma unroll
        for (int c = 0; c < 4; c++) {
            const int xi = x0 + (c & 1), yi = y0 + (c >> 1);
            const bool valid = (xi >= 0) && (xi < kW) && (yi >= 0) && (yi < kH);
            const int xc = min(max(xi, 0), kW - 1), yc = min(max(yi, 0), kH - 1);
            const float wt = ((c & 1) ? dx : 1.f - dx) * ((c >> 1) ? dy : 1.f - dy);
            cwh[o + c]  = __half2half2(__float2half(valid ? wt : 0.f));
            cidx[o + c] = (short)(yc * kW + xc);
        }
    }
    __syncthreads();

    // gather: 8 channels/thread via LDG.128, fp16 corners + fp32 softmax accumulation.
    {
        const int lane = t & 31;
        const int pq   = t >> 5;        // 0..7
        const int c8   = lane & 15;
        const int br   = lane >> 4;
        const __half* vals = (br ? g_vals_geo : g_vals_ctx) + b * kHW * kC + c8 * 8;
        const int gidx = c8 >> 1;       // group = (c8*8)/16
        #pragma unroll
        for (int chunk = 0; chunk < 4; chunk++) {
            const int px = chunk * 8 + pq;
            float a0 = 0.f, a1 = 0.f, a2 = 0.f, a3 = 0.f;
            float a4 = 0.f, a5 = 0.f, a6 = 0.f, a7 = 0.f;
            const __half* wtp = wts + px * 144 + br * 72 + gidx;
            const uint4*  cwp4 = reinterpret_cast<const uint4*>(cwh + (px * 18 + br * 9) * 4);
            const short4* idp4 = reinterpret_cast<const short4*>(cidx + (px * 18 + br * 9) * 4);
            #pragma unroll
            for (int p = 0; p < kP; p++) {
                const float wp = __half2float(wtp[p * 8]);
                const uint4  cu = cwp4[p];
                const short4 iv = idp4[p];
                const __half2 zero = __float2half2_rn(0.f);
                __half2 s01 = zero, s23 = zero, s45 = zero, s67 = zero;
                #pragma unroll
                for (int c = 0; c < 4; c++) {
                    const unsigned cb = (c == 0) ? cu.x : (c == 1) ? cu.y : (c == 2) ? cu.z : cu.w;
                    const int     idx = (c == 0) ? iv.x : (c == 1) ? iv.y : (c == 2) ? iv.z : iv.w;
                    const __half2 ch = *reinterpret_cast<const __half2*>(&cb);
                    const H8 r = *reinterpret_cast<const H8*>(vals + (int)idx * kC);
                    s01 = __hfma2(ch, r.a, s01);
                    s23 = __hfma2(ch, r.b, s23);
                    s45 = __hfma2(ch, r.c, s45);
                    s67 = __hfma2(ch, r.d, s67);
                }
                const float2 f0 = __half22float2(s01), f1 = __half22float2(s23);
                const float2 f2 = __half22float2(s45), f3 = __half22float2(s67);
                a0 = fmaf(wp, f0.x, a0); a1 = fmaf(wp, f0.y, a1);
                a2 = fmaf(wp, f1.x, a2); a3 = fmaf(wp, f1.y, a3);
                a4 = fmaf(wp, f2.x, a4); a5 = fmaf(wp, f2.y, a5);
                a6 = fmaf(wp, f3.x, a6); a7 = fmaf(wp, f3.y, a7);
            }
            const float sc = br ? 1.f : msm[px];
            H8 h;
            h.a = __floats2half2_rn(a0 * sc, a1 * sc);
            h.b = __floats2half2_rn(a2 * sc, a3 * sc);
            h.c = __floats2half2_rn(a4 * sc, a5 * sc);
            h.d = __floats2half2_rn(a6 * sc, a7 * sc);
            // coalesced: whole warp writes one px row (512 B) per chunk
            *reinterpret_cast<H8*>(g_feat + (nb + px) * 256 + (br * 128 + c8 * 8)) = h;
        }
    }
}

// ---------------- kernel 2b: 256 -> 128 output conv, feat staged in smem ----------------
// smem: feat half [64][264] = 33,792 B; 5 CTAs/SM, grid 400 -> single wave
static constexpr int kFT = 264;
static constexpr int kK2bSmem = 33792;

__global__ __launch_bounds__(256, 5) void k2b_outconv(
    const float* __restrict__ out_b, float* __restrict__ d_out)
{
    extern __shared__ unsigned char smraw[];
    __half* feat = reinterpret_cast<__half*>(smraw);

    const int t    = threadIdx.x;
    const int wrp  = t >> 5, lane = t & 31;
    const int nb   = blockIdx.x * 64;
    const int b    = nb / kHW;
    const int hwb  = nb - b * kHW;

    // stage feat tile: 64 rows x 512 B, coalesced cp.async (8 chunks/thread)
    {
        const unsigned f0 = smem_u32(feat);
        #pragma unroll
        for (int i = 0; i < 8; i++) {
            const int idx  = t + i * 256;          // 0..2047
            const int row  = idx >> 5;             // 0..63
            const int chnk = idx & 31;             // 16B chunk
            cp_async16(f0 + (unsigned)(row * kFT * 2 + chnk * 16),
                       g_feat + (nb + row) * 256 + chnk * 8);
        }
        asm volatile("cp.async.commit_group;" ::: "memory");
        asm volatile("cp.async.wait_group 0;" ::: "memory");
        __syncthreads();
    }

    const int o0 = wrp * 16;
    const int r  = lane >> 2;
    const int c2 = (lane & 3) * 2;
    const __half* Arow0 = g_OW16 + (o0 + r) * 256 + c2;
    const __half* Arow1 = Arow0 + 8 * 256;

    float d[8][4];
    #pragma unroll
    for (int nt = 0; nt < 8; nt++)
        #pragma unroll
        for (int q = 0; q < 4; q++) d[nt][q] = 0.f;

    #pragma unroll
    for (int kk = 0; kk < 16; kk++) {
        const unsigned a0 = *reinterpret_cast<const unsigned*>(Arow0 + kk * 16);
        const unsigned a2 = *reinterpret_cast<const unsigned*>(Arow0 + kk * 16 + 8);
        const unsigned a1 = *reinterpret_cast<const unsigned*>(Arow1 + kk * 16);
        const unsigned a3 = *reinterpret_cast<const unsigned*>(Arow1 + kk * 16 + 8);
        #pragma unroll
        for (int nt = 0; nt < 8; nt++) {
            const __half* bp = feat + (nt * 8 + r) * kFT + kk * 16 + c2;
            const unsigned b0 = *reinterpret_cast<const unsigned*>(bp);
            const unsigned b1 = *reinterpret_cast<const unsigned*>(bp + 8);
            mma16816(d[nt][0], d[nt][1], d[nt][2], d[nt][3], a0, a1, a2, a3, b0, b1);
        }
    }
    const float bb0 = out_b[o0 + r];
    const float bb1 = out_b[o0 + r + 8];
    float* obase = d_out + b * kC * kHW + hwb;
    #pragma unroll
    for (int nt = 0; nt < 8; nt++) {
        const int px = nt * 8 + c2;
        *reinterpret_cast<float2*>(obase + (o0 + r) * kHW + px) =
            make_float2(d[nt][0] + bb0, d[nt][1] + bb0);
        *reinterpret_cast<float2*>(obase + (o0 + r + 8) * kHW + px) =
            make_float2(d[nt][2] + bb1, d[nt][3] + bb1);
    }
}

// ---------------- launch ----------------
extern "C" void kernel_launch(void* const* d_in, const int* in_sizes, int n_in,
                              void* d_out, int out_size)
{
    const float* mask      = (const float*)d_in[0];
    const float* match     = (const float*)d_in[1];
    const float* context   = (const float*)d_in[2];
    const float* geometric = (const float*)d_in[3];
    const float* anc_c     = (const float*)d_in[4];
    const float* anc_g     = (const float*)d_in[5];
    const float* ln_g  = (const float*)d_in[6];
    const float* ln_b  = (const float*)d_in[7];
    const float* lnc_g = (const float*)d_in[8];
    const float* lnc_b = (const float*)d_in[9];
    const float* lng_g = (const float*)d_in[10];
    const float* lng_b = (const float*)d_in[11];
    const float* wc_w  = (const float*)d_in[12];
    const float* wc_b  = (const float*)d_in[13];
    const float* wg_w  = (const float*)d_in[14];
    const float* wg_b  = (const float*)d_in[15];
    const float* vc_w  = (const float*)d_in[16];
    const float* vc_b  = (const float*)d_in[17];
    const float* vg_w  = (const float*)d_in[18];
    const float* vg_b  = (const float*)d_in[19];
    const float* out_w = (const float*)d_in[20];
    const float* out_b = (const float*)d_in[21];
    const float* kpc_w = (const float*)d_in[22];
    const float* kpc_b = (const float*)d_in[23];
    const float* kpg_w = (const float*)d_in[24];
    const float* kpg_b = (const float*)d_in[25];
    float* out = (float*)d_out;

    cudaFuncSetAttribute(k1_ln_gemm, cudaFuncAttributeMaxDynamicSharedMemorySize, kK1Smem);
    cudaFuncSetAttribute(k2a_gather, cudaFuncAttributeMaxDynamicSharedMemorySize, kK2aSmem);
    cudaFuncSetAttribute(k2b_outconv, cudaFuncAttributeMaxDynamicSharedMemorySize, kK2bSmem);

    prep_all<<<546, 128>>>(vc_w, vc_b, vg_w, vg_b, wc_w, wc_b, wg_w, wg_b,
                           kpc_w, kpc_b, kpg_w, kpg_b,
                           ln_g, ln_b, lnc_g, lnc_b, lng_g, lng_b, out_w);
    k1_ln_gemm<<<kN / 64, 256, kK1Smem>>>(match, context, geometric, anc_c, anc_g, out, out_size);
    k2a_gather<<<kN / 32, 256, kK2aSmem>>>(mask);
    k2b_outconv<<<kN / 64, 256, kK2bSmem>>>(out_b, out);
}